// round 6
// baseline (speedup 1.0000x reference)
#include <cuda_runtime.h>

#define HID 128
#define HEADS 4
#define DIM 32
#define NT 8
#define ETY 8

#define N_SRC_MAX 200000
#define N_CTR_MAX 100000
#define N_EDGE_MAX 800000
#define OSRC_LEN (N_SRC_MAX + 1024)
#define ODST_LEN (N_CTR_MAX + 1024)

typedef unsigned long long u64;

__device__ __forceinline__ u64 pk2(float x, float y) {
    u64 r; asm("mov.b64 %0,{%1,%2};" : "=l"(r) : "f"(x), "f"(y)); return r;
}
__device__ __forceinline__ void up2(float& x, float& y, u64 v) {
    asm("mov.b64 {%0,%1},%2;" : "=f"(x), "=f"(y) : "l"(v));
}
__device__ __forceinline__ u64 f2fma(u64 a, u64 b, u64 c) {
    u64 d; asm("fma.rn.f32x2 %0,%1,%2,%3;" : "=l"(d) : "l"(a), "l"(b), "l"(c)); return d;
}

// ---------------- scratch (device globals; no runtime allocation) ----------------
__device__ float g_k[(size_t)N_SRC_MAX * HID];
__device__ float g_v[(size_t)N_SRC_MAX * HID];
__device__ float g_q[(size_t)N_CTR_MAX * HID];
__device__ float g_a[(size_t)N_EDGE_MAX * HEADS];   // edge scores
__device__ int   g_dstid[N_EDGE_MAX];
__device__ int   g_eord[N_EDGE_MAX];
__device__ int   g_osrc[OSRC_LEN];
__device__ int   g_odst[ODST_LEN];
__device__ int   g_cnt[16];
__device__ int   g_pos[16];
__device__ int   g_ecnt[8];
__device__ int   g_epos[8];

// ---------------- prep ----------------
__global__ void init_kernel() {
    int i = blockIdx.x * blockDim.x + threadIdx.x;
    int stride = gridDim.x * blockDim.x;
    if (i < 16) { g_cnt[i] = 0; g_pos[i] = 0; }
    if (i < 8)  { g_ecnt[i] = 0; g_epos[i] = 0; }
    for (int j = i; j < OSRC_LEN; j += stride) g_osrc[j] = -1;
    for (int j = i; j < ODST_LEN; j += stride) g_odst[j] = -1;
}

__global__ void hist_all_kernel(const int* __restrict__ ntype, const int* __restrict__ etype,
                                int num_src, int num_center, int num_edge) {
    __shared__ int sc[24];
    if (threadIdx.x < 24) sc[threadIdx.x] = 0;
    __syncthreads();
    int n = blockIdx.x * blockDim.x + threadIdx.x;
    if (n < num_src) {
        int t = ntype[n];
        atomicAdd(&sc[t], 1);
        if (n < num_center) atomicAdd(&sc[8 + t], 1);
    }
    if (n < num_edge) atomicAdd(&sc[16 + etype[n]], 1);
    __syncthreads();
    if (threadIdx.x < 16 && sc[threadIdx.x]) atomicAdd(&g_cnt[threadIdx.x], sc[threadIdx.x]);
    if (threadIdx.x >= 16 && threadIdx.x < 24 && sc[threadIdx.x])
        atomicAdd(&g_ecnt[threadIdx.x - 16], sc[threadIdx.x]);
}

__global__ void offsets_kernel() {
    if (threadIdx.x == 0 && blockIdx.x == 0) {
        int off = 0;
        for (int t = 0; t < 8; t++) { g_pos[t] = off; off += ((g_cnt[t] + 63) >> 6) << 6; }
        off = 0;
        for (int t = 0; t < 8; t++) { g_pos[8 + t] = off; off += ((g_cnt[8 + t] + 63) >> 6) << 6; }
        off = 0;
        for (int t = 0; t < 8; t++) { g_epos[t] = off; off += g_ecnt[t]; }
    }
}

__global__ void scatter_all_kernel(const int* __restrict__ ntype, const int* __restrict__ etype,
                                   int num_src, int num_center, int num_edge) {
    __shared__ int sc[24];
    __shared__ int sb[24];
    if (threadIdx.x < 24) sc[threadIdx.x] = 0;
    __syncthreads();
    int n = blockIdx.x * blockDim.x + threadIdx.x;
    int t = 0, r1 = -1, r2 = -1;
    int te = 0, re = -1;
    if (n < num_src) {
        t = ntype[n];
        r1 = atomicAdd(&sc[t], 1);
        if (n < num_center) r2 = atomicAdd(&sc[8 + t], 1);
    }
    if (n < num_edge) { te = etype[n]; re = atomicAdd(&sc[16 + te], 1); }
    __syncthreads();
    if (threadIdx.x < 16)
        sb[threadIdx.x] = sc[threadIdx.x] ? atomicAdd(&g_pos[threadIdx.x], sc[threadIdx.x]) : 0;
    else if (threadIdx.x < 24)
        sb[threadIdx.x] = sc[threadIdx.x] ? atomicAdd(&g_epos[threadIdx.x - 16], sc[threadIdx.x]) : 0;
    __syncthreads();
    if (r1 >= 0) g_osrc[sb[t] + r1] = n;
    if (r2 >= 0) g_odst[sb[8 + t] + r2] = n;
    if (re >= 0) g_eord[sb[16 + te] + re] = n;
}

// ---------------- typed node projection: dense GEMM on sorted tiles (f32x2) ----------------
__global__ void __launch_bounds__(256, 2) node_gemm_kernel(
    const float* __restrict__ x, const float* __restrict__ W8,
    const int* __restrict__ ntype, int which)
{
    extern __shared__ float sm[];
    float* w_sm = sm;              // 128*128
    float* xT = sm + 128 * 128;    // 128*64
    const int* order = (which == 2) ? g_odst : g_osrc;
    float* outp = (which == 0) ? g_k : (which == 1) ? g_v : g_q;

    const int base = blockIdx.x * 64;
    int n0 = order[base];
    if (n0 < 0) return;
    int t = ntype[n0];
    const int tid = threadIdx.x;

    const float4* W4 = (const float4*)(W8 + (size_t)t * 128 * 128);
    float4* w4 = (float4*)w_sm;
#pragma unroll
    for (int i = 0; i < 16; ++i) w4[tid + 256 * i] = W4[tid + 256 * i];

    int m = tid >> 2, q4 = tid & 3;
    int row = order[base + m];
#pragma unroll
    for (int it = 0; it < 8; ++it) {
        int c = q4 * 4 + it * 16;
        float4 xv = make_float4(0.f, 0.f, 0.f, 0.f);
        if (row >= 0) xv = *(const float4*)(x + (size_t)row * 128 + c);
        xT[(c + 0) * 64 + m] = xv.x;
        xT[(c + 1) * 64 + m] = xv.y;
        xT[(c + 2) * 64 + m] = xv.z;
        xT[(c + 3) * 64 + m] = xv.w;
    }
    __syncthreads();

    const int tm = tid >> 5;
    const int tn = tid & 31;
    u64 acc2[4][4];
#pragma unroll
    for (int i = 0; i < 4; ++i)
#pragma unroll
        for (int j = 0; j < 4; ++j) acc2[i][j] = 0ull;

#pragma unroll 8
    for (int kk = 0; kk < 128; ++kk) {
        const ulonglong2* xp = (const ulonglong2*)(xT + kk * 64 + tm * 8);
        ulonglong2 xa = xp[0];
        ulonglong2 xb = xp[1];
        u64 xs[4] = { xa.x, xa.y, xb.x, xb.y };
        float4 wv = *(const float4*)(w_sm + kk * 128 + tn * 4);
        u64 wd[4] = { pk2(wv.x, wv.x), pk2(wv.y, wv.y), pk2(wv.z, wv.z), pk2(wv.w, wv.w) };
#pragma unroll
        for (int i = 0; i < 4; ++i)
#pragma unroll
            for (int j = 0; j < 4; ++j) acc2[i][j] = f2fma(xs[i], wd[j], acc2[i][j]);
    }

#pragma unroll
    for (int i2 = 0; i2 < 4; ++i2) {
        float r0[4], r1[4];
#pragma unroll
        for (int j = 0; j < 4; ++j) up2(r0[j], r1[j], acc2[i2][j]);
        int m0 = tm * 8 + 2 * i2;
        int ra = order[base + m0], rb = order[base + m0 + 1];
        if (ra >= 0) *(float4*)(outp + (size_t)ra * 128 + tn * 4) = make_float4(r0[0], r0[1], r0[2], r0[3]);
        if (rb >= 0) *(float4*)(outp + (size_t)rb * 128 + tn * 4) = make_float4(r1[0], r1[1], r1[2], r1[3]);
    }
}

// ---------------- dst id fill ----------------
__global__ void fill_dst_kernel(const int* __restrict__ ptr, int C) {
    int c = blockIdx.x * blockDim.x + threadIdx.x;
    if (c >= C) return;
    int e0 = ptr[c], e1 = ptr[c + 1];
    for (int e = e0; e < e1; ++e) g_dstid[e] = c;
}

// ---------------- edge scores: lane-per-edge with coalesced smem staging ----------------
// Per warp chunk of 32 edges (type-sorted): per head, warp stages each edge's 32-float
// k/q slices coalesced into smem (stride 33, conflict-free), then lanes compute from LDS.
#define STG_WARP_FLOATS 2176   // kst 1056 + qst 1056 + sst 32 + cst 32 (as float slots)
__global__ void __launch_bounds__(256, 1) scores_kernel(
    const int* __restrict__ idx, const int* __restrict__ etype,
    const float* __restrict__ a_rel, const float* __restrict__ relptr, int E)
{
    extern __shared__ float A_sm[];   // [8][4][32][32] floats = 128KB, then staging
    __shared__ float rp[32];
    for (int i = threadIdx.x; i < ETY * HEADS * DIM * DIM; i += blockDim.x) A_sm[i] = a_rel[i];
    if (threadIdx.x < 32) rp[threadIdx.x] = relptr[threadIdx.x];
    __syncthreads();

    const int lane = threadIdx.x & 31;
    const int wloc = threadIdx.x >> 5;
    float* kst = A_sm + ETY * HEADS * DIM * DIM + wloc * STG_WARP_FLOATS;
    float* qst = kst + 1056;
    int* sst = (int*)(qst + 1056);
    int* cst = sst + 32;

    const float inv = 0.17677669529663689f; // 1/sqrt(32)
    const int nwarp = (gridDim.x * blockDim.x) >> 5;
    const int wg = (blockIdx.x * blockDim.x + threadIdx.x) >> 5;
    const int nchunk = (E + 31) >> 5;

    for (int ch = wg; ch < nchunk; ch += nwarp) {
        int p = ch * 32 + lane;
        if (p >= E) p = E - 1;                 // duplicate tail edge (identical rewrite, safe)
        int e = g_eord[p];
        int s = idx[e];
        int c = g_dstid[e];
        int et = etype[e];
        sst[lane] = s;
        cst[lane] = c;

        const float* kr = kst + lane * 33;
        const float* qr = qst + lane * 33;
        const float* Ab = A_sm + et * (HEADS * DIM * DIM);
        float outv[4];
#pragma unroll 1
        for (int h = 0; h < 4; ++h) {
            __syncwarp();
            // coalesced staging: one 128B line per (edge, head)
#pragma unroll 4
            for (int j = 0; j < 32; ++j) {
                int sj = sst[j];
                int cj = cst[j];
                kst[j * 33 + lane] = g_k[(size_t)sj * HID + h * 32 + lane];
                qst[j * 33 + lane] = g_q[(size_t)cj * HID + h * 32 + lane];
            }
            __syncwarp();

            u64 kw2[16];
#pragma unroll
            for (int i = 0; i < 16; ++i) kw2[i] = 0ull;
            const ulonglong2* Ar = (const ulonglong2*)(Ab + h * 1024);
#pragma unroll 4
            for (int d = 0; d < 32; ++d) {
                float kd = kr[d];
                u64 kd2 = pk2(kd, kd);
                const ulonglong2* A2 = Ar + (size_t)d * 8;
#pragma unroll
                for (int f = 0; f < 8; ++f) {
                    ulonglong2 aa = A2[f];
                    kw2[2 * f]     = f2fma(kd2, aa.x, kw2[2 * f]);
                    kw2[2 * f + 1] = f2fma(kd2, aa.y, kw2[2 * f + 1]);
                }
            }
            u64 acc = 0ull;
#pragma unroll
            for (int i = 0; i < 16; ++i)
                acc = f2fma(kw2[i], pk2(qr[2 * i], qr[2 * i + 1]), acc);
            float lo, hi; up2(lo, hi, acc);
            outv[h] = (lo + hi) * rp[h * ETY + et] * inv;
        }
        *(float4*)(g_a + (size_t)e * 4) = make_float4(outv[0], outv[1], outv[2], outv[3]);
    }
}

// ---------------- fused softmax + type-rescan aggregation (f32x2 epilogue) ----------------
__global__ void __launch_bounds__(1024, 1) fused_agg_kernel(
    const int* __restrict__ ptr, const int* __restrict__ idx,
    const int* __restrict__ etype, const float* __restrict__ m_rel,
    float* __restrict__ out, int C)
{
    extern __shared__ u64 m2s[];   // [8][32][32] ulonglong2 = 128KB, repacked head-pairs
    // m2s[2*i], m2s[2*i+1] where i = (t*32+dp)*32+d : pk2(M[t,0,dp,d],M[t,1,dp,d]), pk2(M[t,2..],M[t,3..])
    for (int i = threadIdx.x; i < ETY * DIM * DIM; i += blockDim.x) {
        int t = i >> 10, dp = (i >> 5) & 31, d = i & 31;
        const float* Mt = m_rel + (size_t)t * (HEADS * DIM * DIM);
        m2s[2 * i]     = pk2(Mt[(0 * 32 + dp) * 32 + d], Mt[(1 * 32 + dp) * 32 + d]);
        m2s[2 * i + 1] = pk2(Mt[(2 * 32 + dp) * 32 + d], Mt[(3 * 32 + dp) * 32 + d]);
    }
    __syncthreads();

    const unsigned FULL = 0xffffffffu;
    const int lane = threadIdx.x & 31;
    const int w0 = (blockIdx.x * blockDim.x + threadIdx.x) >> 5;
    const int nw = (gridDim.x * blockDim.x) >> 5;

    for (int c = w0; c < C; c += nw) {
        int e0 = ptr[c], e1 = ptr[c + 1];
        float* ob = out + (size_t)c * HID;
        if (e1 <= e0) {
            ob[lane] = 0.f; ob[32 + lane] = 0.f; ob[64 + lane] = 0.f; ob[96 + lane] = 0.f;
            continue;
        }
        int deg = e1 - e0;

        // softmax stats (lane layout: h = lane&3, el = lane>>2)
        int h4 = lane & 3, el = lane >> 2;
        float mx = __int_as_float(0xff800000);
        for (int i = el; i < deg; i += 8) mx = fmaxf(mx, g_a[(size_t)(e0 + i) * 4 + h4]);
        mx = fmaxf(mx, __shfl_xor_sync(FULL, mx, 4));
        mx = fmaxf(mx, __shfl_xor_sync(FULL, mx, 8));
        mx = fmaxf(mx, __shfl_xor_sync(FULL, mx, 16));
        float den = 0.f;
        for (int i = el; i < deg; i += 8) den += __expf(g_a[(size_t)(e0 + i) * 4 + h4] - mx);
        den += __shfl_xor_sync(FULL, den, 4);
        den += __shfl_xor_sync(FULL, den, 8);
        den += __shfl_xor_sync(FULL, den, 16);
        float dinv = 1.f / den;
        float mxh[4], dih[4];
#pragma unroll
        for (int hh = 0; hh < 4; ++hh) {
            mxh[hh] = __shfl_sync(FULL, mx, hh);
            dih[hh] = __shfl_sync(FULL, dinv, hh);
        }

        // present-type mask
        unsigned tm = 0u;
        for (int i = lane; i < deg; i += 32) tm |= (1u << etype[e0 + i]);
        tm = __reduce_or_sync(FULL, tm);

        u64 O01 = 0ull, O23 = 0ull;
#pragma unroll 1
        for (int t = 0; t < 8; ++t) {
            if (!((tm >> t) & 1u)) continue;
            float s0 = 0.f, s1 = 0.f, s2 = 0.f, s3 = 0.f;
            for (int e = e0; e < e1; ++e) {
                if (etype[e] != t) continue;            // warp-uniform branch
                float4 av = *(const float4*)(g_a + (size_t)e * 4);  // broadcast
                const float* vb = g_v + (size_t)idx[e] * HID;
                s0 = fmaf(__expf(av.x - mxh[0]) * dih[0], vb[lane],      s0);
                s1 = fmaf(__expf(av.y - mxh[1]) * dih[1], vb[32 + lane], s1);
                s2 = fmaf(__expf(av.z - mxh[2]) * dih[2], vb[64 + lane], s2);
                s3 = fmaf(__expf(av.w - mxh[3]) * dih[3], vb[96 + lane], s3);
            }
            const ulonglong2* M2 = (const ulonglong2*)(m2s + (size_t)t * 2048);
#pragma unroll 4
            for (int dp = 0; dp < 32; ++dp) {
                float b0 = __shfl_sync(FULL, s0, dp);
                float b1 = __shfl_sync(FULL, s1, dp);
                float b2 = __shfl_sync(FULL, s2, dp);
                float b3 = __shfl_sync(FULL, s3, dp);
                ulonglong2 mm = M2[dp * 32 + lane];
                O01 = f2fma(pk2(b0, b1), mm.x, O01);
                O23 = f2fma(pk2(b2, b3), mm.y, O23);
            }
        }
        float o0, o1, o2, o3;
        up2(o0, o1, O01);
        up2(o2, o3, O23);
        ob[lane]      = o0;
        ob[32 + lane] = o1;
        ob[64 + lane] = o2;
        ob[96 + lane] = o3;
    }
}

// ---------------- host launcher ----------------
extern "C" void kernel_launch(void* const* d_in, const int* in_sizes, int n_in,
                              void* d_out, int out_size)
{
    (void)out_size;
    const float* x     = (const float*)d_in[0];
    const int*   ptr   = (const int*)d_in[1];
    const int*   idx   = (const int*)d_in[2];
    const int*   ntype = (const int*)d_in[3];
    const int*   etype = (const int*)d_in[4];
    int wb = n_in - 6;
    const float* k_lin = (const float*)d_in[wb + 0];
    const float* q_lin = (const float*)d_in[wb + 1];
    const float* v_lin = (const float*)d_in[wb + 2];
    const float* a_rel = (const float*)d_in[wb + 3];
    const float* m_rel = (const float*)d_in[wb + 4];
    const float* relp  = (const float*)d_in[wb + 5];

    int num_src    = in_sizes[3];
    int num_edge   = in_sizes[2];
    int num_center = in_sizes[1] - 1;
    float* out = (float*)d_out;

    const int SCORES_SMEM = 131072 + 8 * STG_WARP_FLOATS * 4;  // A + 8 warps staging
    cudaFuncSetAttribute(node_gemm_kernel, cudaFuncAttributeMaxDynamicSharedMemorySize, 98304);
    cudaFuncSetAttribute(scores_kernel,    cudaFuncAttributeMaxDynamicSharedMemorySize, SCORES_SMEM);
    cudaFuncSetAttribute(fused_agg_kernel, cudaFuncAttributeMaxDynamicSharedMemorySize, 131072);

    int nmax = num_edge > num_src ? num_edge : num_src;
    init_kernel<<<600, 512>>>();
    hist_all_kernel<<<(nmax + 255) / 256, 256>>>(ntype, etype, num_src, num_center, num_edge);
    offsets_kernel<<<1, 32>>>();
    scatter_all_kernel<<<(nmax + 255) / 256, 256>>>(ntype, etype, num_src, num_center, num_edge);
    fill_dst_kernel<<<(num_center + 255) / 256, 256>>>(ptr, num_center);

    int tiles_src = (num_src + 63) / 64 + 8;
    int tiles_dst = (num_center + 63) / 64 + 8;
    node_gemm_kernel<<<tiles_src, 256, 98304>>>(x, k_lin, ntype, 0);
    node_gemm_kernel<<<tiles_src, 256, 98304>>>(x, v_lin, ntype, 1);
    node_gemm_kernel<<<tiles_dst, 256, 98304>>>(x, q_lin, ntype, 2);

    scores_kernel<<<296, 256, SCORES_SMEM>>>(idx, etype, a_rel, relp, num_edge);
    fused_agg_kernel<<<148, 1024, 131072>>>(ptr, idx, etype, m_rel, out, num_center);
}

// round 7
// speedup vs baseline: 1.6300x; 1.6300x over previous
#include <cuda_runtime.h>

#define HID 128
#define HEADS 4
#define DIM 32
#define NT 8
#define ETY 8

#define N_SRC_MAX 200000
#define N_CTR_MAX 100000
#define N_EDGE_MAX 800000
#define OSRC_LEN (N_SRC_MAX + 1024)
#define ODST_LEN (N_CTR_MAX + 1024)

typedef unsigned long long u64;

__device__ __forceinline__ u64 pk2(float x, float y) {
    u64 r; asm("mov.b64 %0,{%1,%2};" : "=l"(r) : "f"(x), "f"(y)); return r;
}
__device__ __forceinline__ void up2(float& x, float& y, u64 v) {
    asm("mov.b64 {%0,%1},%2;" : "=f"(x), "=f"(y) : "l"(v));
}
__device__ __forceinline__ u64 f2fma(u64 a, u64 b, u64 c) {
    u64 d; asm("fma.rn.f32x2 %0,%1,%2,%3;" : "=l"(d) : "l"(a), "l"(b), "l"(c)); return d;
}

// ---------------- scratch (device globals; no runtime allocation) ----------------
__device__ float g_k[(size_t)N_SRC_MAX * HID];
__device__ float g_v[(size_t)N_SRC_MAX * HID];
__device__ float g_q[(size_t)N_CTR_MAX * HID];
__device__ float g_a[(size_t)N_EDGE_MAX * HEADS];   // edge scores
__device__ int   g_dstid[N_EDGE_MAX];
__device__ int   g_eord[N_EDGE_MAX];
__device__ int   g_osrc[OSRC_LEN];
__device__ int   g_odst[ODST_LEN];
__device__ int   g_cnt[16];
__device__ int   g_pos[16];
__device__ int   g_ecnt[8];
__device__ int   g_epos[8];

// ---------------- prep ----------------
__global__ void init_kernel() {
    int i = blockIdx.x * blockDim.x + threadIdx.x;
    int stride = gridDim.x * blockDim.x;
    if (i < 16) { g_cnt[i] = 0; g_pos[i] = 0; }
    if (i < 8)  { g_ecnt[i] = 0; g_epos[i] = 0; }
    for (int j = i; j < OSRC_LEN; j += stride) g_osrc[j] = -1;
    for (int j = i; j < ODST_LEN; j += stride) g_odst[j] = -1;
}

__global__ void hist_all_kernel(const int* __restrict__ ntype, const int* __restrict__ etype,
                                int num_src, int num_center, int num_edge) {
    __shared__ int sc[24];
    if (threadIdx.x < 24) sc[threadIdx.x] = 0;
    __syncthreads();
    int n = blockIdx.x * blockDim.x + threadIdx.x;
    if (n < num_src) {
        int t = ntype[n];
        atomicAdd(&sc[t], 1);
        if (n < num_center) atomicAdd(&sc[8 + t], 1);
    }
    if (n < num_edge) atomicAdd(&sc[16 + etype[n]], 1);
    __syncthreads();
    if (threadIdx.x < 16 && sc[threadIdx.x]) atomicAdd(&g_cnt[threadIdx.x], sc[threadIdx.x]);
    if (threadIdx.x >= 16 && threadIdx.x < 24 && sc[threadIdx.x])
        atomicAdd(&g_ecnt[threadIdx.x - 16], sc[threadIdx.x]);
}

__global__ void offsets_kernel() {
    if (threadIdx.x == 0 && blockIdx.x == 0) {
        int off = 0;
        for (int t = 0; t < 8; t++) { g_pos[t] = off; off += ((g_cnt[t] + 63) >> 6) << 6; }
        off = 0;
        for (int t = 0; t < 8; t++) { g_pos[8 + t] = off; off += ((g_cnt[8 + t] + 63) >> 6) << 6; }
        off = 0;
        for (int t = 0; t < 8; t++) { g_epos[t] = off; off += g_ecnt[t]; }
    }
}

__global__ void scatter_all_kernel(const int* __restrict__ ntype, const int* __restrict__ etype,
                                   int num_src, int num_center, int num_edge) {
    __shared__ int sc[24];
    __shared__ int sb[24];
    if (threadIdx.x < 24) sc[threadIdx.x] = 0;
    __syncthreads();
    int n = blockIdx.x * blockDim.x + threadIdx.x;
    int t = 0, r1 = -1, r2 = -1;
    int te = 0, re = -1;
    if (n < num_src) {
        t = ntype[n];
        r1 = atomicAdd(&sc[t], 1);
        if (n < num_center) r2 = atomicAdd(&sc[8 + t], 1);
    }
    if (n < num_edge) { te = etype[n]; re = atomicAdd(&sc[16 + te], 1); }
    __syncthreads();
    if (threadIdx.x < 16)
        sb[threadIdx.x] = sc[threadIdx.x] ? atomicAdd(&g_pos[threadIdx.x], sc[threadIdx.x]) : 0;
    else if (threadIdx.x < 24)
        sb[threadIdx.x] = sc[threadIdx.x] ? atomicAdd(&g_epos[threadIdx.x - 16], sc[threadIdx.x]) : 0;
    __syncthreads();
    if (r1 >= 0) g_osrc[sb[t] + r1] = n;
    if (r2 >= 0) g_odst[sb[8 + t] + r2] = n;
    if (re >= 0) g_eord[sb[16 + te] + re] = n;
}

// ---------------- typed node projection: dense GEMM on sorted tiles (f32x2) ----------------
__global__ void __launch_bounds__(256, 2) node_gemm_kernel(
    const float* __restrict__ x, const float* __restrict__ W8,
    const int* __restrict__ ntype, int which)
{
    extern __shared__ float sm[];
    float* w_sm = sm;              // 128*128
    float* xT = sm + 128 * 128;    // 128*64
    const int* order = (which == 2) ? g_odst : g_osrc;
    float* outp = (which == 0) ? g_k : (which == 1) ? g_v : g_q;

    const int base = blockIdx.x * 64;
    int n0 = order[base];
    if (n0 < 0) return;
    int t = ntype[n0];
    const int tid = threadIdx.x;

    const float4* W4 = (const float4*)(W8 + (size_t)t * 128 * 128);
    float4* w4 = (float4*)w_sm;
#pragma unroll
    for (int i = 0; i < 16; ++i) w4[tid + 256 * i] = W4[tid + 256 * i];

    int m = tid >> 2, q4 = tid & 3;
    int row = order[base + m];
#pragma unroll
    for (int it = 0; it < 8; ++it) {
        int c = q4 * 4 + it * 16;
        float4 xv = make_float4(0.f, 0.f, 0.f, 0.f);
        if (row >= 0) xv = *(const float4*)(x + (size_t)row * 128 + c);
        xT[(c + 0) * 64 + m] = xv.x;
        xT[(c + 1) * 64 + m] = xv.y;
        xT[(c + 2) * 64 + m] = xv.z;
        xT[(c + 3) * 64 + m] = xv.w;
    }
    __syncthreads();

    const int tm = tid >> 5;
    const int tn = tid & 31;
    u64 acc2[4][4];
#pragma unroll
    for (int i = 0; i < 4; ++i)
#pragma unroll
        for (int j = 0; j < 4; ++j) acc2[i][j] = 0ull;

#pragma unroll 8
    for (int kk = 0; kk < 128; ++kk) {
        const ulonglong2* xp = (const ulonglong2*)(xT + kk * 64 + tm * 8);
        ulonglong2 xa = xp[0];
        ulonglong2 xb = xp[1];
        u64 xs[4] = { xa.x, xa.y, xb.x, xb.y };
        float4 wv = *(const float4*)(w_sm + kk * 128 + tn * 4);
        u64 wd[4] = { pk2(wv.x, wv.x), pk2(wv.y, wv.y), pk2(wv.z, wv.z), pk2(wv.w, wv.w) };
#pragma unroll
        for (int i = 0; i < 4; ++i)
#pragma unroll
            for (int j = 0; j < 4; ++j) acc2[i][j] = f2fma(xs[i], wd[j], acc2[i][j]);
    }

#pragma unroll
    for (int i2 = 0; i2 < 4; ++i2) {
        float r0[4], r1[4];
#pragma unroll
        for (int j = 0; j < 4; ++j) up2(r0[j], r1[j], acc2[i2][j]);
        int m0 = tm * 8 + 2 * i2;
        int ra = order[base + m0], rb = order[base + m0 + 1];
        if (ra >= 0) *(float4*)(outp + (size_t)ra * 128 + tn * 4) = make_float4(r0[0], r0[1], r0[2], r0[3]);
        if (rb >= 0) *(float4*)(outp + (size_t)rb * 128 + tn * 4) = make_float4(r1[0], r1[1], r1[2], r1[3]);
    }
}

// ---------------- dst id fill ----------------
__global__ void fill_dst_kernel(const int* __restrict__ ptr, int C) {
    int c = blockIdx.x * blockDim.x + threadIdx.x;
    if (c >= C) return;
    int e0 = ptr[c], e1 = ptr[c + 1];
    for (int e = e0; e < e1; ++e) g_dstid[e] = c;
}

// ---------------- edge scores: one edge per thread, 2-type smem, high occupancy ----------------
// Edges type-sorted: a 256-edge contiguous chunk spans at most 2 types (type counts >> 256).
// Block loads only those 2 A matrices (32KB) -> 3 blocks/SM instead of 1.
__global__ void __launch_bounds__(256, 3) scores_kernel(
    const int* __restrict__ idx, const int* __restrict__ etype,
    const float* __restrict__ a_rel, const float* __restrict__ relptr, int E)
{
    extern __shared__ float A_sm[];   // 2 * 4096 floats = 32KB
    __shared__ float rp[32];
    __shared__ int t01[2];
    const int tid = threadIdx.x;
    const int p0 = blockIdx.x * 256;
    if (p0 >= E) return;
    if (tid < 32) rp[tid] = relptr[tid];
    if (tid == 0) {
        t01[0] = etype[g_eord[p0]];
        int pl = p0 + 255; if (pl >= E) pl = E - 1;
        t01[1] = etype[g_eord[pl]];
    }
    __syncthreads();
    const int t0 = t01[0], t1 = t01[1];
    {
        const float4* A0g = (const float4*)(a_rel + (size_t)t0 * 4096);
        const float4* A1g = (const float4*)(a_rel + (size_t)t1 * 4096);
        float4* S = (float4*)A_sm;
#pragma unroll
        for (int i = 0; i < 4; ++i) {
            S[tid + 256 * i] = A0g[tid + 256 * i];
            S[1024 + tid + 256 * i] = A1g[tid + 256 * i];
        }
    }
    __syncthreads();

    const int p = p0 + tid;
    if (p >= E) return;
    const float inv = 0.17677669529663689f; // 1/sqrt(32)
    int e = g_eord[p];
    int s = idx[e];
    int et = etype[e];
    int c = g_dstid[e];
    const float4* kp = (const float4*)(g_k + (size_t)s * HID);
    const ulonglong2* qp = (const ulonglong2*)(g_q + (size_t)c * HID);
    // generic pointer: smem in the common case, global fallback if chunk spans >2 types
    const float* Ab = (et == t0) ? A_sm : (et == t1 ? A_sm + 4096 : a_rel + (size_t)et * 4096);
    float outv[4];
#pragma unroll 1
    for (int h = 0; h < 4; ++h) {
        u64 kw2[16];
#pragma unroll
        for (int i = 0; i < 16; ++i) kw2[i] = 0ull;
        const ulonglong2* Ar = (const ulonglong2*)(Ab + h * 1024);
#pragma unroll 1
        for (int dg = 0; dg < 8; ++dg) {
            float4 kv = kp[h * 8 + dg];
            float kd[4] = { kv.x, kv.y, kv.z, kv.w };
#pragma unroll
            for (int j = 0; j < 4; ++j) {
                u64 kd2 = pk2(kd[j], kd[j]);
                const ulonglong2* A2 = Ar + (size_t)(dg * 4 + j) * 8;
#pragma unroll
                for (int f = 0; f < 8; ++f) {
                    ulonglong2 aa = A2[f];
                    kw2[2 * f]     = f2fma(kd2, aa.x, kw2[2 * f]);
                    kw2[2 * f + 1] = f2fma(kd2, aa.y, kw2[2 * f + 1]);
                }
            }
        }
        u64 acc = 0ull;
#pragma unroll
        for (int f = 0; f < 8; ++f) {
            ulonglong2 qq = qp[h * 8 + f];
            acc = f2fma(kw2[2 * f], qq.x, acc);
            acc = f2fma(kw2[2 * f + 1], qq.y, acc);
        }
        float lo, hi; up2(lo, hi, acc);
        outv[h] = (lo + hi) * rp[h * ETY + et] * inv;
    }
    *(float4*)(g_a + (size_t)e * 4) = make_float4(outv[0], outv[1], outv[2], outv[3]);
}

// ---------------- fused softmax + type-bucketed aggregation: warp per center ----------------
// Register buckets sa[t][h] via switch (round-4 variant, best so far) + f32x2 epilogue.
__global__ void __launch_bounds__(1024, 1) fused_agg_kernel(
    const int* __restrict__ ptr, const int* __restrict__ idx,
    const int* __restrict__ etype, const float* __restrict__ m_rel,
    float* __restrict__ out, int C)
{
    extern __shared__ u64 m2s[];   // [8][32][32] ulonglong2 = 128KB, head-pair packed
    for (int i = threadIdx.x; i < ETY * DIM * DIM; i += blockDim.x) {
        int t = i >> 10, dp = (i >> 5) & 31, d = i & 31;
        const float* Mt = m_rel + (size_t)t * (HEADS * DIM * DIM);
        m2s[2 * i]     = pk2(Mt[(0 * 32 + dp) * 32 + d], Mt[(1 * 32 + dp) * 32 + d]);
        m2s[2 * i + 1] = pk2(Mt[(2 * 32 + dp) * 32 + d], Mt[(3 * 32 + dp) * 32 + d]);
    }
    __syncthreads();

    const unsigned FULL = 0xffffffffu;
    const int lane = threadIdx.x & 31;
    const int w0 = (blockIdx.x * blockDim.x + threadIdx.x) >> 5;
    const int nw = (gridDim.x * blockDim.x) >> 5;

    for (int c = w0; c < C; c += nw) {
        int e0 = ptr[c], e1 = ptr[c + 1];
        float* ob = out + (size_t)c * HID;
        if (e1 <= e0) {
            ob[lane] = 0.f; ob[32 + lane] = 0.f; ob[64 + lane] = 0.f; ob[96 + lane] = 0.f;
            continue;
        }
        int deg = e1 - e0;

        // softmax stats (lane layout: h = lane&3, el = lane>>2)
        int h4 = lane & 3, el = lane >> 2;
        float mx = __int_as_float(0xff800000);
        for (int i = el; i < deg; i += 8) mx = fmaxf(mx, g_a[(size_t)(e0 + i) * 4 + h4]);
        mx = fmaxf(mx, __shfl_xor_sync(FULL, mx, 4));
        mx = fmaxf(mx, __shfl_xor_sync(FULL, mx, 8));
        mx = fmaxf(mx, __shfl_xor_sync(FULL, mx, 16));
        float den = 0.f;
        for (int i = el; i < deg; i += 8) den += __expf(g_a[(size_t)(e0 + i) * 4 + h4] - mx);
        den += __shfl_xor_sync(FULL, den, 4);
        den += __shfl_xor_sync(FULL, den, 8);
        den += __shfl_xor_sync(FULL, den, 16);
        float dinv = 1.f / den;
        float mxh[4], dih[4];
#pragma unroll
        for (int hh = 0; hh < 4; ++hh) {
            mxh[hh] = __shfl_sync(FULL, mx, hh);
            dih[hh] = __shfl_sync(FULL, dinv, hh);
        }

        // per-type accumulation: sa[t][h], lane = d
        float sa[8][4];
#pragma unroll
        for (int t = 0; t < 8; ++t)
#pragma unroll
            for (int h = 0; h < 4; ++h) sa[t][h] = 0.f;
        unsigned tm = 0u;

        for (int e = e0; e < e1; ++e) {
            int s = idx[e];
            int et = etype[e];
            float4 av = *(const float4*)(g_a + (size_t)e * 4);
            float al0 = __expf(av.x - mxh[0]) * dih[0];
            float al1 = __expf(av.y - mxh[1]) * dih[1];
            float al2 = __expf(av.z - mxh[2]) * dih[2];
            float al3 = __expf(av.w - mxh[3]) * dih[3];
            const float* vb = g_v + (size_t)s * HID;
            float v0 = vb[lane];
            float v1 = vb[32 + lane];
            float v2 = vb[64 + lane];
            float v3 = vb[96 + lane];
            tm |= (1u << et);
#define ACC_CASE(T) case T: \
            sa[T][0] = fmaf(al0, v0, sa[T][0]); \
            sa[T][1] = fmaf(al1, v1, sa[T][1]); \
            sa[T][2] = fmaf(al2, v2, sa[T][2]); \
            sa[T][3] = fmaf(al3, v3, sa[T][3]); break;
            switch (et) {
                ACC_CASE(0) ACC_CASE(1) ACC_CASE(2) ACC_CASE(3)
                ACC_CASE(4) ACC_CASE(5) ACC_CASE(6) ACC_CASE(7)
            }
#undef ACC_CASE
        }

        // f32x2 epilogue: out[h,d] += sum_d' sa[t][h][d'] * M[t,h,d',d]
        u64 O01 = 0ull, O23 = 0ull;
#pragma unroll 1
        for (int t = 0; t < 8; ++t) {
            if (!((tm >> t) & 1u)) continue;
            float a0, a1, a2, a3;
            switch (t) {
                case 0: a0 = sa[0][0]; a1 = sa[0][1]; a2 = sa[0][2]; a3 = sa[0][3]; break;
                case 1: a0 = sa[1][0]; a1 = sa[1][1]; a2 = sa[1][2]; a3 = sa[1][3]; break;
                case 2: a0 = sa[2][0]; a1 = sa[2][1]; a2 = sa[2][2]; a3 = sa[2][3]; break;
                case 3: a0 = sa[3][0]; a1 = sa[3][1]; a2 = sa[3][2]; a3 = sa[3][3]; break;
                case 4: a0 = sa[4][0]; a1 = sa[4][1]; a2 = sa[4][2]; a3 = sa[4][3]; break;
                case 5: a0 = sa[5][0]; a1 = sa[5][1]; a2 = sa[5][2]; a3 = sa[5][3]; break;
                case 6: a0 = sa[6][0]; a1 = sa[6][1]; a2 = sa[6][2]; a3 = sa[6][3]; break;
                default: a0 = sa[7][0]; a1 = sa[7][1]; a2 = sa[7][2]; a3 = sa[7][3]; break;
            }
            const ulonglong2* M2 = (const ulonglong2*)(m2s + (size_t)t * 2048);
#pragma unroll 4
            for (int dp = 0; dp < 32; ++dp) {
                float b0 = __shfl_sync(FULL, a0, dp);
                float b1 = __shfl_sync(FULL, a1, dp);
                float b2 = __shfl_sync(FULL, a2, dp);
                float b3 = __shfl_sync(FULL, a3, dp);
                ulonglong2 mm = M2[dp * 32 + lane];
                O01 = f2fma(pk2(b0, b1), mm.x, O01);
                O23 = f2fma(pk2(b2, b3), mm.y, O23);
            }
        }
        float o0, o1, o2, o3;
        up2(o0, o1, O01);
        up2(o2, o3, O23);
        ob[lane]      = o0;
        ob[32 + lane] = o1;
        ob[64 + lane] = o2;
        ob[96 + lane] = o3;
    }
}

// ---------------- host launcher ----------------
extern "C" void kernel_launch(void* const* d_in, const int* in_sizes, int n_in,
                              void* d_out, int out_size)
{
    (void)out_size;
    const float* x     = (const float*)d_in[0];
    const int*   ptr   = (const int*)d_in[1];
    const int*   idx   = (const int*)d_in[2];
    const int*   ntype = (const int*)d_in[3];
    const int*   etype = (const int*)d_in[4];
    int wb = n_in - 6;
    const float* k_lin = (const float*)d_in[wb + 0];
    const float* q_lin = (const float*)d_in[wb + 1];
    const float* v_lin = (const float*)d_in[wb + 2];
    const float* a_rel = (const float*)d_in[wb + 3];
    const float* m_rel = (const float*)d_in[wb + 4];
    const float* relp  = (const float*)d_in[wb + 5];

    int num_src    = in_sizes[3];
    int num_edge   = in_sizes[2];
    int num_center = in_sizes[1] - 1;
    float* out = (float*)d_out;

    cudaFuncSetAttribute(node_gemm_kernel, cudaFuncAttributeMaxDynamicSharedMemorySize, 98304);
    cudaFuncSetAttribute(scores_kernel,    cudaFuncAttributeMaxDynamicSharedMemorySize, 32768);
    cudaFuncSetAttribute(fused_agg_kernel, cudaFuncAttributeMaxDynamicSharedMemorySize, 131072);

    int nmax = num_edge > num_src ? num_edge : num_src;
    init_kernel<<<600, 512>>>();
    hist_all_kernel<<<(nmax + 255) / 256, 256>>>(ntype, etype, num_src, num_center, num_edge);
    offsets_kernel<<<1, 32>>>();
    scatter_all_kernel<<<(nmax + 255) / 256, 256>>>(ntype, etype, num_src, num_center, num_edge);
    fill_dst_kernel<<<(num_center + 255) / 256, 256>>>(ptr, num_center);

    int tiles_src = (num_src + 63) / 64 + 8;
    int tiles_dst = (num_center + 63) / 64 + 8;
    node_gemm_kernel<<<tiles_src, 256, 98304>>>(x, k_lin, ntype, 0);
    node_gemm_kernel<<<tiles_src, 256, 98304>>>(x, v_lin, ntype, 1);
    node_gemm_kernel<<<tiles_dst, 256, 98304>>>(x, q_lin, ntype, 2);

    scores_kernel<<<(num_edge + 255) / 256, 256, 32768>>>(idx, etype, a_rel, relp, num_edge);
    fused_agg_kernel<<<148, 1024, 131072>>>(ptr, idx, etype, m_rel, out, num_center);
}

// round 8
// speedup vs baseline: 2.0700x; 1.2699x over previous
#include <cuda_runtime.h>

#define HID 128
#define HEADS 4
#define DIM 32
#define NT 8
#define ETY 8

#define N_SRC_MAX 200000
#define N_CTR_MAX 100000
#define N_EDGE_MAX 800000
#define OSRC_LEN (N_SRC_MAX + 1024)
#define ODST_LEN (N_CTR_MAX + 1024)

typedef unsigned long long u64;

__device__ __forceinline__ u64 pk2(float x, float y) {
    u64 r; asm("mov.b64 %0,{%1,%2};" : "=l"(r) : "f"(x), "f"(y)); return r;
}
__device__ __forceinline__ void up2(float& x, float& y, u64 v) {
    asm("mov.b64 {%0,%1},%2;" : "=f"(x), "=f"(y) : "l"(v));
}
__device__ __forceinline__ u64 f2fma(u64 a, u64 b, u64 c) {
    u64 d; asm("fma.rn.f32x2 %0,%1,%2,%3;" : "=l"(d) : "l"(a), "l"(b), "l"(c)); return d;
}
__device__ __forceinline__ float tf32r(float x) {
    unsigned u; asm("cvt.rna.tf32.f32 %0, %1;" : "=r"(u) : "f"(x));
    return __uint_as_float(u);
}
__device__ __forceinline__ void mma_tf32(float* c, const unsigned* a, unsigned b0, unsigned b1) {
    asm("mma.sync.aligned.m16n8k8.row.col.f32.tf32.tf32.f32 "
        "{%0,%1,%2,%3}, {%4,%5,%6,%7}, {%8,%9}, {%0,%1,%2,%3};"
        : "+f"(c[0]), "+f"(c[1]), "+f"(c[2]), "+f"(c[3])
        : "r"(a[0]), "r"(a[1]), "r"(a[2]), "r"(a[3]), "r"(b0), "r"(b1));
}

// ---------------- scratch (device globals; no runtime allocation) ----------------
__device__ float g_k[(size_t)N_SRC_MAX * HID];
__device__ float g_v[(size_t)N_SRC_MAX * HID];
__device__ float g_q[(size_t)N_CTR_MAX * HID];
__device__ float g_a[(size_t)N_EDGE_MAX * HEADS];   // edge scores
__device__ int   g_dstid[N_EDGE_MAX];
__device__ int   g_eord[N_EDGE_MAX];
__device__ int   g_osrc[OSRC_LEN];
__device__ int   g_odst[ODST_LEN];
__device__ int   g_cnt[16];
__device__ int   g_pos[16];
__device__ int   g_ecnt[8];
__device__ int   g_epos[8];

// ---------------- prep ----------------
__global__ void init_kernel() {
    int i = blockIdx.x * blockDim.x + threadIdx.x;
    int stride = gridDim.x * blockDim.x;
    if (i < 16) { g_cnt[i] = 0; g_pos[i] = 0; }
    if (i < 8)  { g_ecnt[i] = 0; g_epos[i] = 0; }
    for (int j = i; j < OSRC_LEN; j += stride) g_osrc[j] = -1;
    for (int j = i; j < ODST_LEN; j += stride) g_odst[j] = -1;
}

__global__ void hist_all_kernel(const int* __restrict__ ntype, const int* __restrict__ etype,
                                int num_src, int num_center, int num_edge) {
    __shared__ int sc[24];
    if (threadIdx.x < 24) sc[threadIdx.x] = 0;
    __syncthreads();
    int n = blockIdx.x * blockDim.x + threadIdx.x;
    if (n < num_src) {
        int t = ntype[n];
        atomicAdd(&sc[t], 1);
        if (n < num_center) atomicAdd(&sc[8 + t], 1);
    }
    if (n < num_edge) atomicAdd(&sc[16 + etype[n]], 1);
    __syncthreads();
    if (threadIdx.x < 16 && sc[threadIdx.x]) atomicAdd(&g_cnt[threadIdx.x], sc[threadIdx.x]);
    if (threadIdx.x >= 16 && threadIdx.x < 24 && sc[threadIdx.x])
        atomicAdd(&g_ecnt[threadIdx.x - 16], sc[threadIdx.x]);
}

__global__ void offsets_kernel() {
    if (threadIdx.x == 0 && blockIdx.x == 0) {
        int off = 0;
        for (int t = 0; t < 8; t++) { g_pos[t] = off; off += ((g_cnt[t] + 63) >> 6) << 6; }
        off = 0;
        for (int t = 0; t < 8; t++) { g_pos[8 + t] = off; off += ((g_cnt[8 + t] + 63) >> 6) << 6; }
        off = 0;
        for (int t = 0; t < 8; t++) { g_epos[t] = off; off += g_ecnt[t]; }
    }
}

__global__ void scatter_all_kernel(const int* __restrict__ ntype, const int* __restrict__ etype,
                                   int num_src, int num_center, int num_edge) {
    __shared__ int sc[24];
    __shared__ int sb[24];
    if (threadIdx.x < 24) sc[threadIdx.x] = 0;
    __syncthreads();
    int n = blockIdx.x * blockDim.x + threadIdx.x;
    int t = 0, r1 = -1, r2 = -1;
    int te = 0, re = -1;
    if (n < num_src) {
        t = ntype[n];
        r1 = atomicAdd(&sc[t], 1);
        if (n < num_center) r2 = atomicAdd(&sc[8 + t], 1);
    }
    if (n < num_edge) { te = etype[n]; re = atomicAdd(&sc[16 + te], 1); }
    __syncthreads();
    if (threadIdx.x < 16)
        sb[threadIdx.x] = sc[threadIdx.x] ? atomicAdd(&g_pos[threadIdx.x], sc[threadIdx.x]) : 0;
    else if (threadIdx.x < 24)
        sb[threadIdx.x] = sc[threadIdx.x] ? atomicAdd(&g_epos[threadIdx.x - 16], sc[threadIdx.x]) : 0;
    __syncthreads();
    if (r1 >= 0) g_osrc[sb[t] + r1] = n;
    if (r2 >= 0) g_odst[sb[8 + t] + r2] = n;
    if (re >= 0) g_eord[sb[16 + te] + re] = n;
}

// ---------------- typed node projection: tf32 tensor-core GEMM on sorted tiles ----------------
// Tile: 64 nodes x 128 out, K=128. 8 warps in 2(M)x4(N); warp = 32x32 via m16n8k8 mma.
#define XS_STRIDE 132
#define WS_STRIDE 136
#define GEMM_SMEM ((64 * XS_STRIDE + 128 * WS_STRIDE) * 4)

__global__ void __launch_bounds__(256, 2) node_gemm_kernel(
    const float* __restrict__ x, const float* __restrict__ W8,
    const int* __restrict__ ntype, int which)
{
    extern __shared__ float sm[];
    float* xs = sm;                     // [64][132] tf32
    float* ws = sm + 64 * XS_STRIDE;    // [128][136] tf32
    const int* order = (which == 2) ? g_odst : g_osrc;
    float* outp = (which == 0) ? g_k : (which == 1) ? g_v : g_q;

    const int base = blockIdx.x * 64;
    int n0 = order[base];
    if (n0 < 0) return;
    int t = ntype[n0];
    const int tid = threadIdx.x;

    // stage W[t] (tf32-converted): 4096 float4s
    const float4* Wg = (const float4*)(W8 + (size_t)t * 16384);
#pragma unroll
    for (int i = 0; i < 16; ++i) {
        int e4 = tid + i * 256;
        float4 w = Wg[e4];
        int k = e4 >> 5, n = (e4 & 31) << 2;
        float4 o = make_float4(tf32r(w.x), tf32r(w.y), tf32r(w.z), tf32r(w.w));
        *(float4*)(ws + k * WS_STRIDE + n) = o;
    }
    // stage x rows (tf32-converted)
    {
        int m = tid >> 2, q4 = tid & 3;
        int row = order[base + m];
#pragma unroll
        for (int it = 0; it < 8; ++it) {
            int k = q4 * 4 + it * 16;
            float4 xv = make_float4(0.f, 0.f, 0.f, 0.f);
            if (row >= 0) xv = *(const float4*)(x + (size_t)row * 128 + k);
            float4 o = make_float4(tf32r(xv.x), tf32r(xv.y), tf32r(xv.z), tf32r(xv.w));
            *(float4*)(xs + m * XS_STRIDE + k) = o;
        }
    }
    __syncthreads();

    const int lane = tid & 31, wid = tid >> 5;
    const int wm = (wid >> 2) * 32;   // 0 / 32
    const int wn = (wid & 3) * 32;    // 0..96
    const int g = lane >> 2, tig = lane & 3;

    float acc[2][4][4];
#pragma unroll
    for (int mt = 0; mt < 2; ++mt)
#pragma unroll
        for (int nt = 0; nt < 4; ++nt)
#pragma unroll
            for (int j = 0; j < 4; ++j) acc[mt][nt][j] = 0.f;

#pragma unroll 4
    for (int ks = 0; ks < 16; ++ks) {
        int kb = ks * 8;
        unsigned a[2][4];
#pragma unroll
        for (int mt = 0; mt < 2; ++mt) {
            const float* xr = xs + (wm + mt * 16 + g) * XS_STRIDE + kb;
            const float* xr8 = xr + 8 * XS_STRIDE;
            a[mt][0] = __float_as_uint(xr[tig]);
            a[mt][1] = __float_as_uint(xr8[tig]);
            a[mt][2] = __float_as_uint(xr[tig + 4]);
            a[mt][3] = __float_as_uint(xr8[tig + 4]);
        }
#pragma unroll
        for (int nt = 0; nt < 4; ++nt) {
            const float* wr = ws + (kb + tig) * WS_STRIDE + wn + nt * 8 + g;
            unsigned b0 = __float_as_uint(wr[0]);
            unsigned b1 = __float_as_uint(wr[4 * WS_STRIDE]);
            mma_tf32(acc[0][nt], a[0], b0, b1);
            mma_tf32(acc[1][nt], a[1], b0, b1);
        }
    }

    // epilogue: c0=[g][2tig] c1=[g][2tig+1] c2=[g+8][2tig] c3=[g+8][2tig+1]
#pragma unroll
    for (int mt = 0; mt < 2; ++mt) {
        int r0 = order[base + wm + mt * 16 + g];
        int r1 = order[base + wm + mt * 16 + g + 8];
#pragma unroll
        for (int nt = 0; nt < 4; ++nt) {
            int cn = wn + nt * 8 + 2 * tig;
            if (r0 >= 0) {
                float2 o = make_float2(acc[mt][nt][0], acc[mt][nt][1]);
                *(float2*)(outp + (size_t)r0 * 128 + cn) = o;
            }
            if (r1 >= 0) {
                float2 o = make_float2(acc[mt][nt][2], acc[mt][nt][3]);
                *(float2*)(outp + (size_t)r1 * 128 + cn) = o;
            }
        }
    }
}

// ---------------- dst id fill ----------------
__global__ void fill_dst_kernel(const int* __restrict__ ptr, int C) {
    int c = blockIdx.x * blockDim.x + threadIdx.x;
    if (c >= C) return;
    int e0 = ptr[c], e1 = ptr[c + 1];
    for (int e = e0; e < e1; ++e) g_dstid[e] = c;
}

// ---------------- edge scores: lane-per-edge, etype-sorted (R4 variant) ----------------
__global__ void __launch_bounds__(512, 1) scores_kernel(
    const int* __restrict__ idx, const int* __restrict__ etype,
    const float* __restrict__ a_rel, const float* __restrict__ relptr, int E)
{
    extern __shared__ float A_sm[];   // 128KB
    __shared__ float rp[32];
    for (int i = threadIdx.x; i < ETY * HEADS * DIM * DIM; i += blockDim.x) A_sm[i] = a_rel[i];
    if (threadIdx.x < 32) rp[threadIdx.x] = relptr[threadIdx.x];
    __syncthreads();

    const float inv = 0.17677669529663689f; // 1/sqrt(32)
    int stride = gridDim.x * blockDim.x;
    for (int p = blockIdx.x * blockDim.x + threadIdx.x; p < E; p += stride) {
        int e = g_eord[p];
        int s = idx[e];
        int et = etype[e];
        int c = g_dstid[e];
        const float4* kp = (const float4*)(g_k + (size_t)s * HID);
        const ulonglong2* qp = (const ulonglong2*)(g_q + (size_t)c * HID);
        const float* Ab = A_sm + et * (HEADS * DIM * DIM);
        float outv[4];
#pragma unroll 1
        for (int h = 0; h < 4; ++h) {
            u64 kw2[16];
#pragma unroll
            for (int i = 0; i < 16; ++i) kw2[i] = 0ull;
            const ulonglong2* Ar = (const ulonglong2*)(Ab + h * 1024);
#pragma unroll 1
            for (int dg = 0; dg < 8; ++dg) {
                float4 kv = kp[h * 8 + dg];
                float kd[4] = { kv.x, kv.y, kv.z, kv.w };
#pragma unroll
                for (int j = 0; j < 4; ++j) {
                    u64 kd2 = pk2(kd[j], kd[j]);
                    const ulonglong2* A2 = Ar + (size_t)(dg * 4 + j) * 8;
#pragma unroll
                    for (int f = 0; f < 8; ++f) {
                        ulonglong2 aa = A2[f];
                        kw2[2 * f]     = f2fma(kd2, aa.x, kw2[2 * f]);
                        kw2[2 * f + 1] = f2fma(kd2, aa.y, kw2[2 * f + 1]);
                    }
                }
            }
            u64 acc = 0ull;
#pragma unroll
            for (int f = 0; f < 8; ++f) {
                ulonglong2 qq = qp[h * 8 + f];
                acc = f2fma(kw2[2 * f], qq.x, acc);
                acc = f2fma(kw2[2 * f + 1], qq.y, acc);
            }
            float lo, hi; up2(lo, hi, acc);
            outv[h] = (lo + hi) * rp[h * ETY + et] * inv;
        }
        *(float4*)(g_a + (size_t)e * 4) = make_float4(outv[0], outv[1], outv[2], outv[3]);
    }
}

// ---------------- fused softmax + type-bucketed aggregation (R4 variant) ----------------
__global__ void __launch_bounds__(1024, 1) fused_agg_kernel(
    const int* __restrict__ ptr, const int* __restrict__ idx,
    const int* __restrict__ etype, const float* __restrict__ m_rel,
    float* __restrict__ out, int C)
{
    extern __shared__ float M_sm[];   // [8][4][32][32] = 128KB
    for (int i = threadIdx.x; i < ETY * HEADS * DIM * DIM; i += blockDim.x) M_sm[i] = m_rel[i];
    __syncthreads();

    const unsigned FULL = 0xffffffffu;
    const int lane = threadIdx.x & 31;
    const int w0 = (blockIdx.x * blockDim.x + threadIdx.x) >> 5;
    const int nw = (gridDim.x * blockDim.x) >> 5;

    for (int c = w0; c < C; c += nw) {
        int e0 = ptr[c], e1 = ptr[c + 1];
        float* ob = out + (size_t)c * HID;
        if (e1 <= e0) {
            ob[lane] = 0.f; ob[32 + lane] = 0.f; ob[64 + lane] = 0.f; ob[96 + lane] = 0.f;
            continue;
        }
        int deg = e1 - e0;

        int h4 = lane & 3, el = lane >> 2;
        float mx = __int_as_float(0xff800000);
        for (int i = el; i < deg; i += 8) mx = fmaxf(mx, g_a[(size_t)(e0 + i) * 4 + h4]);
        mx = fmaxf(mx, __shfl_xor_sync(FULL, mx, 4));
        mx = fmaxf(mx, __shfl_xor_sync(FULL, mx, 8));
        mx = fmaxf(mx, __shfl_xor_sync(FULL, mx, 16));
        float den = 0.f;
        for (int i = el; i < deg; i += 8) den += __expf(g_a[(size_t)(e0 + i) * 4 + h4] - mx);
        den += __shfl_xor_sync(FULL, den, 4);
        den += __shfl_xor_sync(FULL, den, 8);
        den += __shfl_xor_sync(FULL, den, 16);
        float dinv = 1.f / den;
        float mxh[4], dih[4];
#pragma unroll
        for (int hh = 0; hh < 4; ++hh) {
            mxh[hh] = __shfl_sync(FULL, mx, hh);
            dih[hh] = __shfl_sync(FULL, dinv, hh);
        }

        float sa[8][4];
#pragma unroll
        for (int t = 0; t < 8; ++t)
#pragma unroll
            for (int h = 0; h < 4; ++h) sa[t][h] = 0.f;
        unsigned tm = 0u;

        for (int e = e0; e < e1; ++e) {
            int s = idx[e];
            int et = etype[e];
            float4 av = *(const float4*)(g_a + (size_t)e * 4);
            float al0 = __expf(av.x - mxh[0]) * dih[0];
            float al1 = __expf(av.y - mxh[1]) * dih[1];
            float al2 = __expf(av.z - mxh[2]) * dih[2];
            float al3 = __expf(av.w - mxh[3]) * dih[3];
            const float* vb = g_v + (size_t)s * HID;
            float v0 = vb[lane];
            float v1 = vb[32 + lane];
            float v2 = vb[64 + lane];
            float v3 = vb[96 + lane];
            tm |= (1u << et);
#define ACC_CASE(T) case T: \
            sa[T][0] = fmaf(al0, v0, sa[T][0]); \
            sa[T][1] = fmaf(al1, v1, sa[T][1]); \
            sa[T][2] = fmaf(al2, v2, sa[T][2]); \
            sa[T][3] = fmaf(al3, v3, sa[T][3]); break;
            switch (et) {
                ACC_CASE(0) ACC_CASE(1) ACC_CASE(2) ACC_CASE(3)
                ACC_CASE(4) ACC_CASE(5) ACC_CASE(6) ACC_CASE(7)
            }
#undef ACC_CASE
        }

        float o0 = 0.f, o1 = 0.f, o2 = 0.f, o3 = 0.f;
#pragma unroll 1
        for (int t = 0; t < 8; ++t) {
            if (!((tm >> t) & 1u)) continue;
            float a0, a1, a2, a3;
            switch (t) {
                case 0: a0 = sa[0][0]; a1 = sa[0][1]; a2 = sa[0][2]; a3 = sa[0][3]; break;
                case 1: a0 = sa[1][0]; a1 = sa[1][1]; a2 = sa[1][2]; a3 = sa[1][3]; break;
                case 2: a0 = sa[2][0]; a1 = sa[2][1]; a2 = sa[2][2]; a3 = sa[2][3]; break;
                case 3: a0 = sa[3][0]; a1 = sa[3][1]; a2 = sa[3][2]; a3 = sa[3][3]; break;
                case 4: a0 = sa[4][0]; a1 = sa[4][1]; a2 = sa[4][2]; a3 = sa[4][3]; break;
                case 5: a0 = sa[5][0]; a1 = sa[5][1]; a2 = sa[5][2]; a3 = sa[5][3]; break;
                case 6: a0 = sa[6][0]; a1 = sa[6][1]; a2 = sa[6][2]; a3 = sa[6][3]; break;
                default: a0 = sa[7][0]; a1 = sa[7][1]; a2 = sa[7][2]; a3 = sa[7][3]; break;
            }
            const float* Mb = M_sm + t * (HEADS * DIM * DIM);
#pragma unroll
            for (int dp = 0; dp < 32; ++dp) {
                float b0 = __shfl_sync(FULL, a0, dp);
                float b1 = __shfl_sync(FULL, a1, dp);
                float b2 = __shfl_sync(FULL, a2, dp);
                float b3 = __shfl_sync(FULL, a3, dp);
                o0 = fmaf(b0, Mb[(0 * 32 + dp) * 32 + lane], o0);
                o1 = fmaf(b1, Mb[(1 * 32 + dp) * 32 + lane], o1);
                o2 = fmaf(b2, Mb[(2 * 32 + dp) * 32 + lane], o2);
                o3 = fmaf(b3, Mb[(3 * 32 + dp) * 32 + lane], o3);
            }
        }
        ob[lane]      = o0;
        ob[32 + lane] = o1;
        ob[64 + lane] = o2;
        ob[96 + lane] = o3;
    }
}

// ---------------- host launcher ----------------
extern "C" void kernel_launch(void* const* d_in, const int* in_sizes, int n_in,
                              void* d_out, int out_size)
{
    (void)out_size;
    const float* x     = (const float*)d_in[0];
    const int*   ptr   = (const int*)d_in[1];
    const int*   idx   = (const int*)d_in[2];
    const int*   ntype = (const int*)d_in[3];
    const int*   etype = (const int*)d_in[4];
    int wb = n_in - 6;
    const float* k_lin = (const float*)d_in[wb + 0];
    const float* q_lin = (const float*)d_in[wb + 1];
    const float* v_lin = (const float*)d_in[wb + 2];
    const float* a_rel = (const float*)d_in[wb + 3];
    const float* m_rel = (const float*)d_in[wb + 4];
    const float* relp  = (const float*)d_in[wb + 5];

    int num_src    = in_sizes[3];
    int num_edge   = in_sizes[2];
    int num_center = in_sizes[1] - 1;
    float* out = (float*)d_out;

    cudaFuncSetAttribute(node_gemm_kernel, cudaFuncAttributeMaxDynamicSharedMemorySize, GEMM_SMEM);
    cudaFuncSetAttribute(scores_kernel,    cudaFuncAttributeMaxDynamicSharedMemorySize, 131072);
    cudaFuncSetAttribute(fused_agg_kernel, cudaFuncAttributeMaxDynamicSharedMemorySize, 131072);

    int nmax = num_edge > num_src ? num_edge : num_src;
    init_kernel<<<600, 512>>>();
    hist_all_kernel<<<(nmax + 255) / 256, 256>>>(ntype, etype, num_src, num_center, num_edge);
    offsets_kernel<<<1, 32>>>();
    scatter_all_kernel<<<(nmax + 255) / 256, 256>>>(ntype, etype, num_src, num_center, num_edge);
    fill_dst_kernel<<<(num_center + 255) / 256, 256>>>(ptr, num_center);

    int tiles_src = (num_src + 63) / 64 + 8;
    int tiles_dst = (num_center + 63) / 64 + 8;
    node_gemm_kernel<<<tiles_src, 256, GEMM_SMEM>>>(x, k_lin, ntype, 0);
    node_gemm_kernel<<<tiles_src, 256, GEMM_SMEM>>>(x, v_lin, ntype, 1);
    node_gemm_kernel<<<tiles_dst, 256, GEMM_SMEM>>>(x, q_lin, ntype, 2);

    scores_kernel<<<148, 512, 131072>>>(idx, etype, a_rel, relp, num_edge);
    fused_agg_kernel<<<148, 1024, 131072>>>(ptr, idx, etype, m_rel, out, num_center);
}